// round 13
// baseline (speedup 1.0000x reference)
#include <cuda_runtime.h>
#include <cuda_bf16.h>
#include <cstdint>

// Problem constants
#define BB   64
#define TT   1024
#define HH   256
#define DIN  136
#define G4   1024
#define KP   144
#define CL   8
#define BPC  8
#define JPC  32

// ---------------- scratch ----------------
__device__ __align__(16) float g_proj[2][(size_t)TT * G4 * BB];
__device__ __align__(16) float g_hs[(size_t)TT * 2 * HH * BB];
__device__ __align__(16) __nv_bfloat16 g_xhi[(size_t)TT * BB * KP];
__device__ __align__(16) __nv_bfloat16 g_xlo[(size_t)TT * BB * KP];
__device__ __align__(16) __nv_bfloat16 g_whi[2][(size_t)G4 * KP];
__device__ __align__(16) __nv_bfloat16 g_wlo[2][(size_t)G4 * KP];

// ---------------- activations ----------------
__device__ __forceinline__ float sigf(float x) { return 1.0f / (1.0f + __expf(-x)); }
__device__ __forceinline__ float tanh_fast(float x) {
    float xx = fminf(fmaxf(x, -10.0f), 10.0f);
    float e = __expf(2.0f * xx);
    return (e - 1.0f) / (e + 1.0f);
}

// ---------------- DSMEM helpers ----------------
__device__ __forceinline__ void st_cluster_f4(uint32_t laddr, uint32_t rank, uint4 v) {
    asm volatile(
        "{\n\t.reg .b32 r;\n\t"
        "mapa.shared::cluster.u32 r, %0, %1;\n\t"
        "st.shared::cluster.v4.b32 [r], {%2, %3, %4, %5};\n\t}"
        :: "r"(laddr), "r"(rank), "r"(v.x), "r"(v.y), "r"(v.z), "r"(v.w) : "memory");
}
__device__ __forceinline__ void mbar_arrive_rank(uint32_t local_mbar, uint32_t rank) {
    asm volatile(
        "{\n\t.reg .b32 remAddr;\n\t"
        "mapa.shared::cluster.u32 remAddr, %0, %1;\n\t"
        "mbarrier.arrive.release.cluster.shared::cluster.b64 _, [remAddr];\n\t}"
        :: "r"(local_mbar), "r"(rank) : "memory");
}
__device__ __forceinline__ void mbar_wait_parity(uint32_t mbar, unsigned parity) {
    unsigned done = 0;
    do {
        asm volatile(
            "{\n\t.reg .pred p;\n\t"
            "mbarrier.try_wait.parity.acquire.cluster.shared::cta.b64 p, [%1], %2, 0x989680;\n\t"
            "selp.b32 %0, 1, 0, p;\n\t}"
            : "=r"(done) : "r"(mbar), "r"(parity) : "memory");
    } while (!done);
}

// ---------------- warp-level bf16 MMA ----------------
__device__ __forceinline__ void mma16816(float* d, const uint32_t* a,
                                         uint32_t b0, uint32_t b1) {
    asm volatile(
        "mma.sync.aligned.m16n8k16.row.col.f32.bf16.bf16.f32 "
        "{%0,%1,%2,%3}, {%4,%5,%6,%7}, {%8,%9}, {%0,%1,%2,%3};"
        : "+f"(d[0]), "+f"(d[1]), "+f"(d[2]), "+f"(d[3])
        : "r"(a[0]), "r"(a[1]), "r"(a[2]), "r"(a[3]), "r"(b0), "r"(b1));
}
__device__ __forceinline__ uint32_t pack_bf16x2(float lo, float hi) {
    __nv_bfloat162 t = __floats2bfloat162_rn(lo, hi);
    return *(uint32_t*)&t;
}

// ---------------- conversion kernels ----------------
__global__ void conv_x_kernel(const float* __restrict__ x) {
    const int t = blockIdx.x;
    for (int idx = threadIdx.x; idx < BB * KP; idx += 256) {
        int b = idx / KP, k = idx - b * KP;
        float v = (k < DIN) ? __ldg(x + ((size_t)b * TT + t) * DIN + k) : 0.0f;
        __nv_bfloat16 hi = __float2bfloat16_rn(v);
        __nv_bfloat16 lo = __float2bfloat16_rn(v - __bfloat162float(hi));
        size_t o = ((size_t)t * BB + b) * KP + k;
        g_xhi[o] = hi; g_xlo[o] = lo;
    }
}
__global__ void conv_w_kernel(const float* __restrict__ wf, const float* __restrict__ wb) {
    const int row = blockIdx.x;
    const int dir = blockIdx.y;
    const float* w = dir ? wb : wf;
    for (int k = threadIdx.x; k < KP; k += 160) {
        float v = (k < DIN) ? __ldg(w + (size_t)row * DIN + k) : 0.0f;
        __nv_bfloat16 hi = __float2bfloat16_rn(v);
        __nv_bfloat16 lo = __float2bfloat16_rn(v - __bfloat162float(hi));
        size_t o = (size_t)row * KP + k;
        g_whi[dir][o] = hi; g_wlo[dir][o] = lo;
    }
}

// ---------------- input projection via warp MMA (R10/R11, known-good) -------------
#define PBST 304
__global__ void __launch_bounds__(128, 3) proj_mma_kernel(
    const float* __restrict__ bih_f, const float* __restrict__ bih_b)
{
    extern __shared__ char psm[];
    char* sbhi = psm;
    char* sblo = psm + 19456;

    const int r0  = blockIdx.x * 64;
    const int t   = blockIdx.y;
    const int dir = blockIdx.z;
    const int tid = threadIdx.x;
    const int w   = tid >> 5;
    const int lane = tid & 31;

    const int m1 = (w << 4) + (lane >> 2);
    const int m2 = m1 + 8;
    const __nv_bfloat16* wh1 = g_whi[dir] + (size_t)(r0 + m1) * KP;
    const __nv_bfloat16* wh2 = g_whi[dir] + (size_t)(r0 + m2) * KP;
    const __nv_bfloat16* wl1 = g_wlo[dir] + (size_t)(r0 + m1) * KP;
    const __nv_bfloat16* wl2 = g_wlo[dir] + (size_t)(r0 + m2) * KP;
    uint32_t ahi[9][4], alo[9][4];
#pragma unroll
    for (int ch = 0; ch < 9; ch++) {
        int kb = ch * 16 + (lane & 3) * 2;
        ahi[ch][0] = *(const uint32_t*)(wh1 + kb);
        ahi[ch][1] = *(const uint32_t*)(wh2 + kb);
        ahi[ch][2] = *(const uint32_t*)(wh1 + kb + 8);
        ahi[ch][3] = *(const uint32_t*)(wh2 + kb + 8);
        alo[ch][0] = *(const uint32_t*)(wl1 + kb);
        alo[ch][1] = *(const uint32_t*)(wl2 + kb);
        alo[ch][2] = *(const uint32_t*)(wl1 + kb + 8);
        alo[ch][3] = *(const uint32_t*)(wl2 + kb + 8);
    }

    {
        const uint4* xh = (const uint4*)(g_xhi + (size_t)t * BB * KP);
        const uint4* xl = (const uint4*)(g_xlo + (size_t)t * BB * KP);
        for (int idx = tid; idx < 64 * 18; idx += 128) {
            int b = idx / 18, kk = idx - b * 18;
            uint4 vh = __ldg(xh + b * 18 + kk);
            uint4 vl = __ldg(xl + b * 18 + kk);
            *(uint4*)(sbhi + b * PBST + kk * 16) = vh;
            *(uint4*)(sblo + b * PBST + kk * 16) = vl;
        }
    }
    __syncthreads();

    float acc[8][4];
#pragma unroll
    for (int nt = 0; nt < 8; nt++)
#pragma unroll
        for (int i = 0; i < 4; i++) acc[nt][i] = 0.0f;

    const char* bhp = sbhi + (lane >> 2) * PBST + (lane & 3) * 4;
    const char* blp = sblo + (lane >> 2) * PBST + (lane & 3) * 4;
#pragma unroll
    for (int ch = 0; ch < 9; ch++) {
#pragma unroll
        for (int nt = 0; nt < 8; nt++) {
            int off = nt * 8 * PBST + ch * 32;
            uint32_t bh0 = *(const uint32_t*)(bhp + off);
            uint32_t bh1 = *(const uint32_t*)(bhp + off + 16);
            uint32_t bl0 = *(const uint32_t*)(blp + off);
            uint32_t bl1 = *(const uint32_t*)(blp + off + 16);
            mma16816(acc[nt], ahi[ch], bh0, bh1);
            mma16816(acc[nt], ahi[ch], bl0, bl1);
            mma16816(acc[nt], alo[ch], bh0, bh1);
        }
    }

    const float* bi = dir ? bih_b : bih_f;
    float bias1 = __ldg(bi + r0 + m1);
    float bias2 = __ldg(bi + r0 + m2);
    float* dst = g_proj[dir] + (size_t)t * G4 * BB;
    const int n0 = (lane & 3) * 2;
#pragma unroll
    for (int nt = 0; nt < 8; nt++) {
        int n = nt * 8 + n0;
        *(float2*)(dst + (size_t)(r0 + m1) * BB + n) =
            make_float2(acc[nt][0] + bias1, acc[nt][1] + bias1);
        *(float2*)(dst + (size_t)(r0 + m2) * BB + n) =
            make_float2(acc[nt][2] + bias2, acc[nt][3] + bias2);
    }
}

// ---------------- clustered recurrent scan: fragment-order B, mbarrier sync -------
// B tile per parity: [16 chunks][32 lanes][16 B] = 8192 B.
// Thread 'lane' reads ONE uint4 per chunk = {bh0, bh1, bl0, bl1} (R9 fragment values).
// SMEM: [0..16384) B[2 parities]; [16384..17408) stg (own 2 chunks);
//       [17408..22016) gsm [128][9] f32; [22016..22032) mbar[2].
#define PAR_SZ   8192
#define SM_STG   16384
#define SM_GSM   17408
#define SM_MB    22016
#define SM_TOTAL 22528

__global__ void __launch_bounds__(256, 1) __cluster_dims__(CL, 1, 1)
scan_kernel(const float* __restrict__ whh_f, const float* __restrict__ whh_b,
            const float* __restrict__ bhh_f, const float* __restrict__ bhh_b)
{
    extern __shared__ char smc[];
    float* gsm = (float*)(smc + SM_GSM);
    const uint32_t smem_u32 = (uint32_t)__cvta_generic_to_shared(smc);

    const int cid  = blockIdx.x >> 3;
    const int rank = blockIdx.x & 7;
    const int dir  = cid >> 3;
    const int b0   = (cid & 7) * BPC;
    const int j0   = rank * JPC;
    const float* whh = dir ? whh_b : whh_f;
    const float* bhh = dir ? bhh_b : bhh_f;
    const int tid  = threadIdx.x;
    const int w    = tid >> 5;
    const int lane = tid & 31;

    // W hi/lo A-fragments in registers (R9-validated layout)
    uint32_t ahi[16][4], alo[16][4];
    {
        const int m1 = (w << 4) + (lane >> 2);
        const int m2 = m1 + 8;
        const int g1 = (m1 >> 5) * 256 + j0 + (m1 & 31);
        const int g2 = (m2 >> 5) * 256 + j0 + (m2 & 31);
        const float* wr1 = whh + (size_t)g1 * HH;
        const float* wr2 = whh + (size_t)g2 * HH;
#pragma unroll
        for (int ks = 0; ks < 16; ks++) {
            int kb = ks * 16 + (lane & 3) * 2;
#pragma unroll
            for (int half = 0; half < 2; half++) {
                int k = kb + half * 8;
                float a0 = __ldg(wr1 + k),  a1 = __ldg(wr1 + k + 1);
                float b0f = __ldg(wr2 + k), b1f = __ldg(wr2 + k + 1);
                __nv_bfloat16 a0h = __float2bfloat16_rn(a0);
                __nv_bfloat16 a1h = __float2bfloat16_rn(a1);
                __nv_bfloat16 b0h = __float2bfloat16_rn(b0f);
                __nv_bfloat16 b1h = __float2bfloat16_rn(b1f);
                ahi[ks][half * 2 + 0] = pack_bf16x2(__bfloat162float(a0h), __bfloat162float(a1h));
                ahi[ks][half * 2 + 1] = pack_bf16x2(__bfloat162float(b0h), __bfloat162float(b1h));
                alo[ks][half * 2 + 0] = pack_bf16x2(a0 - __bfloat162float(a0h),
                                                    a1 - __bfloat162float(a1h));
                alo[ks][half * 2 + 1] = pack_bf16x2(b0f - __bfloat162float(b0h),
                                                    b1f - __bfloat162float(b1h));
            }
        }
    }

    const int jj = tid >> 3;
    const int b  = tid & 7;
    float bh[4];
#pragma unroll
    for (int g = 0; g < 4; g++) bh[g] = __ldg(bhh + g * 256 + j0 + jj);

    // staging address for this thread's h (fragment-order within own 2 chunks)
    const int kq   = jj & 15;                       // k within chunk
    const int cloc = jj >> 4;                       // local chunk 0/1
    const int lt   = b * 4 + ((kq & 7) >> 1);       // target lane
    const int wrd  = kq >> 3;                       // word 0/1 (hi)
    const int byt  = kq & 1;
    char* stg_hi = smc + SM_STG + cloc * 512 + lt * 16 + wrd * 4 + byt * 2;

    // zero both B parities; init mbarriers
    for (int i = tid; i < (2 * PAR_SZ) / 4; i += 256) ((uint32_t*)smc)[i] = 0u;
    if (tid == 0) {
        asm volatile("mbarrier.init.shared.b64 [%0], %1;" :: "r"(smem_u32 + SM_MB), "r"(CL) : "memory");
        asm volatile("mbarrier.init.shared.b64 [%0], %1;" :: "r"(smem_u32 + SM_MB + 8), "r"(CL) : "memory");
    }
    __syncthreads();
    asm volatile("barrier.cluster.arrive.aligned;" ::: "memory");
    asm volatile("barrier.cluster.wait.aligned;" ::: "memory");

    const int rl1 = (w << 4) + (lane >> 2);
    const int rl2 = rl1 + 8;
    const int n0  = (lane & 3) * 2;

    float c = 0.0f;
    float pf[4];
    {
        const int t0 = dir ? (TT - 1) : 0;
#pragma unroll
        for (int g = 0; g < 4; g++)
            pf[g] = __ldg(g_proj[dir] + ((size_t)t0 * G4 + g * 256 + j0 + jj) * BB + b0 + b);
    }

    for (int s = 0; s < TT; ++s) {
        const int t = dir ? (TT - 1 - s) : s;
        const int p = s & 1;

        // wait for B[p] completeness (8 arrivals from step s-1)
        if (s > 0) mbar_wait_parity(smem_u32 + SM_MB + p * 8, (unsigned)(((s - 1) >> 1) & 1));

        // MMA on B[p]: one LDS.128 per chunk -> {bh0, bh1, bl0, bl1}
        const char* bp = smc + p * PAR_SZ + lane * 16;
        float accA[4] = {0, 0, 0, 0}, accB[4] = {0, 0, 0, 0}, accC[4] = {0, 0, 0, 0};
#pragma unroll
        for (int ks = 0; ks < 16; ks++) {
            uint4 q = *(const uint4*)(bp + ks * 512);
            mma16816(accA, ahi[ks], q.x, q.y);
            mma16816(accB, ahi[ks], q.z, q.w);
            mma16816(accC, alo[ks], q.x, q.y);
        }
        gsm[rl1 * 9 + n0]     = accA[0] + accB[0] + accC[0];
        gsm[rl1 * 9 + n0 + 1] = accA[1] + accB[1] + accC[1];
        gsm[rl2 * 9 + n0]     = accA[2] + accB[2] + accC[2];
        gsm[rl2 * 9 + n0 + 1] = accA[3] + accB[3] + accC[3];
        __syncthreads();

        // cell: thread (jj, b)
        float gv[4];
#pragma unroll
        for (int g = 0; g < 4; g++)
            gv[g] = pf[g] + bh[g] + gsm[(g * 32 + jj) * 9 + b];
        float i_ = sigf(gv[0]);
        float f_ = sigf(gv[1]);
        float g_ = tanh_fast(gv[2]);
        float o_ = sigf(gv[3]);
        c = f_ * c + i_ * g_;
        float h = o_ * tanh_fast(c);

        g_hs[((size_t)t * 512 + dir * 256 + j0 + jj) * BB + b0 + b] = h;

        // stage own h in fragment order (hi word, lo word at +8B)
        {
            __nv_bfloat16 hh = __float2bfloat16_rn(h);
            __nv_bfloat16 hl = __float2bfloat16_rn(h - __bfloat162float(hh));
            *(__nv_bfloat16*)stg_hi       = hh;
            *(__nv_bfloat16*)(stg_hi + 8) = hl;
        }
        __syncthreads();

        if (s + 1 < TT) {
            // scatter own 1KB slice into B[p^1] of all 8 ranks (2 uint4/thread)
#pragma unroll
            for (int rep = 0; rep < 2; rep++) {
                int i = tid + rep * 256;
                int chunk = i & 63;
                int ro = i >> 6;
                uint4 v = *(const uint4*)(smc + SM_STG + chunk * 16);
                uint32_t dstoff = (uint32_t)((p ^ 1) * PAR_SZ + rank * 1024 + chunk * 16);
                st_cluster_f4(smem_u32 + dstoff, (uint32_t)((rank + ro) & 7), v);
            }
            // fence + all-arrive on mb[p^1] of every rank
            if (tid == 0) {
                asm volatile("fence.acq_rel.cluster;" ::: "memory");
#pragma unroll
                for (uint32_t r = 0; r < CL; r++)
                    mbar_arrive_rank(smem_u32 + SM_MB + (p ^ 1) * 8, r);
            }
            // prefetch next proj (overlaps peers' scatter + next wait)
            const int tn = dir ? (TT - 2 - s) : (s + 1);
#pragma unroll
            for (int g = 0; g < 4; g++)
                pf[g] = __ldg(g_proj[dir] + ((size_t)tn * G4 + g * 256 + j0 + jj) * BB + b0 + b);
        }
    }

    // exit barrier: no CTA may leave while peers' DSMEM traffic is in flight
    asm volatile("barrier.cluster.arrive.aligned;" ::: "memory");
    asm volatile("barrier.cluster.wait.aligned;" ::: "memory");
}

// ---------------- final FC ----------------
__global__ void __launch_bounds__(320) fc_kernel(
    const float* __restrict__ fcw, const float* __restrict__ fcb,
    float* __restrict__ out)
{
    const int t = blockIdx.x;
    const int o = threadIdx.x / 64;
    const int b = threadIdx.x & 63;
    const float* hp = g_hs + (size_t)t * 512 * BB + b;
    const float* wp = fcw + o * 512;
    float acc = 0.0f;
#pragma unroll 8
    for (int j = 0; j < 512; j++)
        acc += hp[(size_t)j * BB] * __ldg(wp + j);
    out[((size_t)b * TT + t) * 5 + o] = acc + __ldg(fcb + o);
}

// ---------------- launch ----------------
extern "C" void kernel_launch(void* const* d_in, const int* in_sizes, int n_in,
                              void* d_out, int out_size)
{
    const float* x      = (const float*)d_in[0];
    const float* wih_f  = (const float*)d_in[1];
    const float* whh_f  = (const float*)d_in[2];
    const float* bih_f  = (const float*)d_in[3];
    const float* bhh_f  = (const float*)d_in[4];
    const float* wih_b  = (const float*)d_in[5];
    const float* whh_b  = (const float*)d_in[6];
    const float* bih_b  = (const float*)d_in[7];
    const float* bhh_b  = (const float*)d_in[8];
    const float* fcw    = (const float*)d_in[9];
    const float* fcb    = (const float*)d_in[10];
    float* out = (float*)d_out;

    const int pm_smem = 2 * 19456;
    cudaFuncSetAttribute(proj_mma_kernel, cudaFuncAttributeMaxDynamicSharedMemorySize, pm_smem);
    cudaFuncSetAttribute(scan_kernel, cudaFuncAttributeMaxDynamicSharedMemorySize, SM_TOTAL);

    conv_x_kernel<<<TT, 256>>>(x);
    conv_w_kernel<<<dim3(G4, 2), 160>>>(wih_f, wih_b);

    dim3 pg(16, TT, 2);
    proj_mma_kernel<<<pg, 128, pm_smem>>>(bih_f, bih_b);

    scan_kernel<<<128, 256, SM_TOTAL>>>(whh_f, whh_b, bhh_f, bhh_b);

    fc_kernel<<<TT, 320>>>(fcw, fcb, out);
}

// round 14
// speedup vs baseline: 1.7996x; 1.7996x over previous
#include <cuda_runtime.h>
#include <cuda_bf16.h>
#include <cstdint>

// Problem constants
#define BB   64
#define TT   1024
#define HH   256
#define DIN  136
#define G4   1024
#define KP   144
#define CL   8
#define BPC  8
#define JPC  32

// ---------------- scratch ----------------
__device__ __align__(16) float g_proj[2][(size_t)TT * G4 * BB];
__device__ __align__(16) float g_hs[(size_t)TT * 2 * HH * BB];
__device__ __align__(16) __nv_bfloat16 g_xhi[(size_t)TT * BB * KP];
__device__ __align__(16) __nv_bfloat16 g_xlo[(size_t)TT * BB * KP];
__device__ __align__(16) __nv_bfloat16 g_whi[2][(size_t)G4 * KP];
__device__ __align__(16) __nv_bfloat16 g_wlo[2][(size_t)G4 * KP];

// ---------------- activations ----------------
__device__ __forceinline__ float sigf(float x) { return 1.0f / (1.0f + __expf(-x)); }
__device__ __forceinline__ float tanh_fast(float x) {
    float xx = fminf(fmaxf(x, -10.0f), 10.0f);
    float e = __expf(2.0f * xx);
    return (e - 1.0f) / (e + 1.0f);
}

// ---------------- DSMEM float4 store to peer rank ----------------
__device__ __forceinline__ void st_cluster_f4(uint32_t laddr, uint32_t rank, uint4 v) {
    asm volatile(
        "{\n\t.reg .b32 r;\n\t"
        "mapa.shared::cluster.u32 r, %0, %1;\n\t"
        "st.shared::cluster.v4.b32 [r], {%2, %3, %4, %5};\n\t}"
        :: "r"(laddr), "r"(rank), "r"(v.x), "r"(v.y), "r"(v.z), "r"(v.w) : "memory");
}

// ---------------- warp-level bf16 MMA ----------------
__device__ __forceinline__ void mma16816(float* d, const uint32_t* a,
                                         uint32_t b0, uint32_t b1) {
    asm volatile(
        "mma.sync.aligned.m16n8k16.row.col.f32.bf16.bf16.f32 "
        "{%0,%1,%2,%3}, {%4,%5,%6,%7}, {%8,%9}, {%0,%1,%2,%3};"
        : "+f"(d[0]), "+f"(d[1]), "+f"(d[2]), "+f"(d[3])
        : "r"(a[0]), "r"(a[1]), "r"(a[2]), "r"(a[3]), "r"(b0), "r"(b1));
}
__device__ __forceinline__ uint32_t pack_bf16x2(float lo, float hi) {
    __nv_bfloat162 t = __floats2bfloat162_rn(lo, hi);
    return *(uint32_t*)&t;
}

// ---------------- conversion kernels ----------------
__global__ void conv_x_kernel(const float* __restrict__ x) {
    const int t = blockIdx.x;
    for (int idx = threadIdx.x; idx < BB * KP; idx += 256) {
        int b = idx / KP, k = idx - b * KP;
        float v = (k < DIN) ? __ldg(x + ((size_t)b * TT + t) * DIN + k) : 0.0f;
        __nv_bfloat16 hi = __float2bfloat16_rn(v);
        __nv_bfloat16 lo = __float2bfloat16_rn(v - __bfloat162float(hi));
        size_t o = ((size_t)t * BB + b) * KP + k;
        g_xhi[o] = hi; g_xlo[o] = lo;
    }
}
__global__ void conv_w_kernel(const float* __restrict__ wf, const float* __restrict__ wb) {
    const int row = blockIdx.x;
    const int dir = blockIdx.y;
    const float* w = dir ? wb : wf;
    for (int k = threadIdx.x; k < KP; k += 160) {
        float v = (k < DIN) ? __ldg(w + (size_t)row * DIN + k) : 0.0f;
        __nv_bfloat16 hi = __float2bfloat16_rn(v);
        __nv_bfloat16 lo = __float2bfloat16_rn(v - __bfloat162float(hi));
        size_t o = (size_t)row * KP + k;
        g_whi[dir][o] = hi; g_wlo[dir][o] = lo;
    }
}

// ---------------- input projection via warp MMA (R10/R11, known-good) -------------
#define PBST 304
__global__ void __launch_bounds__(128, 3) proj_mma_kernel(
    const float* __restrict__ bih_f, const float* __restrict__ bih_b)
{
    extern __shared__ char psm[];
    char* sbhi = psm;
    char* sblo = psm + 19456;

    const int r0  = blockIdx.x * 64;
    const int t   = blockIdx.y;
    const int dir = blockIdx.z;
    const int tid = threadIdx.x;
    const int w   = tid >> 5;
    const int lane = tid & 31;

    const int m1 = (w << 4) + (lane >> 2);
    const int m2 = m1 + 8;
    const __nv_bfloat16* wh1 = g_whi[dir] + (size_t)(r0 + m1) * KP;
    const __nv_bfloat16* wh2 = g_whi[dir] + (size_t)(r0 + m2) * KP;
    const __nv_bfloat16* wl1 = g_wlo[dir] + (size_t)(r0 + m1) * KP;
    const __nv_bfloat16* wl2 = g_wlo[dir] + (size_t)(r0 + m2) * KP;
    uint32_t ahi[9][4], alo[9][4];
#pragma unroll
    for (int ch = 0; ch < 9; ch++) {
        int kb = ch * 16 + (lane & 3) * 2;
        ahi[ch][0] = *(const uint32_t*)(wh1 + kb);
        ahi[ch][1] = *(const uint32_t*)(wh2 + kb);
        ahi[ch][2] = *(const uint32_t*)(wh1 + kb + 8);
        ahi[ch][3] = *(const uint32_t*)(wh2 + kb + 8);
        alo[ch][0] = *(const uint32_t*)(wl1 + kb);
        alo[ch][1] = *(const uint32_t*)(wl2 + kb);
        alo[ch][2] = *(const uint32_t*)(wl1 + kb + 8);
        alo[ch][3] = *(const uint32_t*)(wl2 + kb + 8);
    }

    {
        const uint4* xh = (const uint4*)(g_xhi + (size_t)t * BB * KP);
        const uint4* xl = (const uint4*)(g_xlo + (size_t)t * BB * KP);
        for (int idx = tid; idx < 64 * 18; idx += 128) {
            int b = idx / 18, kk = idx - b * 18;
            uint4 vh = __ldg(xh + b * 18 + kk);
            uint4 vl = __ldg(xl + b * 18 + kk);
            *(uint4*)(sbhi + b * PBST + kk * 16) = vh;
            *(uint4*)(sblo + b * PBST + kk * 16) = vl;
        }
    }
    __syncthreads();

    float acc[8][4];
#pragma unroll
    for (int nt = 0; nt < 8; nt++)
#pragma unroll
        for (int i = 0; i < 4; i++) acc[nt][i] = 0.0f;

    const char* bhp = sbhi + (lane >> 2) * PBST + (lane & 3) * 4;
    const char* blp = sblo + (lane >> 2) * PBST + (lane & 3) * 4;
#pragma unroll
    for (int ch = 0; ch < 9; ch++) {
#pragma unroll
        for (int nt = 0; nt < 8; nt++) {
            int off = nt * 8 * PBST + ch * 32;
            uint32_t bh0 = *(const uint32_t*)(bhp + off);
            uint32_t bh1 = *(const uint32_t*)(bhp + off + 16);
            uint32_t bl0 = *(const uint32_t*)(blp + off);
            uint32_t bl1 = *(const uint32_t*)(blp + off + 16);
            mma16816(acc[nt], ahi[ch], bh0, bh1);
            mma16816(acc[nt], ahi[ch], bl0, bl1);
            mma16816(acc[nt], alo[ch], bh0, bh1);
        }
    }

    const float* bi = dir ? bih_b : bih_f;
    float bias1 = __ldg(bi + r0 + m1);
    float bias2 = __ldg(bi + r0 + m2);
    float* dst = g_proj[dir] + (size_t)t * G4 * BB;
    const int n0 = (lane & 3) * 2;
#pragma unroll
    for (int nt = 0; nt < 8; nt++) {
        int n = nt * 8 + n0;
        *(float2*)(dst + (size_t)(r0 + m1) * BB + n) =
            make_float2(acc[nt][0] + bias1, acc[nt][1] + bias1);
        *(float2*)(dst + (size_t)(r0 + m2) * BB + n) =
            make_float2(acc[nt][2] + bias2, acc[nt][3] + bias2);
    }
}

// ---------------- clustered recurrent scan: fragment-order B + barrier.cluster ----
// B tile per parity: [16 chunks][32 lanes][16 B] = 8192 B. Thread reads ONE uint4
// per chunk = {bh0, bh1, bl0, bl1} (bit-identical to R9-validated fragments).
// Sync: split barrier.cluster.arrive / proj-prefetch / wait (R11-proven).
// SMEM: [0..16384) B[2 parities]; [16384..17408) stg; [17408..22016) gsm [128][9].
#define PAR_SZ   8192
#define SM_STG   16384
#define SM_GSM   17408
#define SM_TOTAL 22016

__global__ void __launch_bounds__(256, 1) __cluster_dims__(CL, 1, 1)
scan_kernel(const float* __restrict__ whh_f, const float* __restrict__ whh_b,
            const float* __restrict__ bhh_f, const float* __restrict__ bhh_b)
{
    extern __shared__ char smc[];
    float* gsm = (float*)(smc + SM_GSM);
    const uint32_t smem_u32 = (uint32_t)__cvta_generic_to_shared(smc);

    const int cid  = blockIdx.x >> 3;
    const int rank = blockIdx.x & 7;
    const int dir  = cid >> 3;
    const int b0   = (cid & 7) * BPC;
    const int j0   = rank * JPC;
    const float* whh = dir ? whh_b : whh_f;
    const float* bhh = dir ? bhh_b : bhh_f;
    const int tid  = threadIdx.x;
    const int w    = tid >> 5;
    const int lane = tid & 31;

    // W hi/lo A-fragments in registers (R9-validated layout)
    uint32_t ahi[16][4], alo[16][4];
    {
        const int m1 = (w << 4) + (lane >> 2);
        const int m2 = m1 + 8;
        const int g1 = (m1 >> 5) * 256 + j0 + (m1 & 31);
        const int g2 = (m2 >> 5) * 256 + j0 + (m2 & 31);
        const float* wr1 = whh + (size_t)g1 * HH;
        const float* wr2 = whh + (size_t)g2 * HH;
#pragma unroll
        for (int ks = 0; ks < 16; ks++) {
            int kb = ks * 16 + (lane & 3) * 2;
#pragma unroll
            for (int half = 0; half < 2; half++) {
                int k = kb + half * 8;
                float a0 = __ldg(wr1 + k),  a1 = __ldg(wr1 + k + 1);
                float b0f = __ldg(wr2 + k), b1f = __ldg(wr2 + k + 1);
                __nv_bfloat16 a0h = __float2bfloat16_rn(a0);
                __nv_bfloat16 a1h = __float2bfloat16_rn(a1);
                __nv_bfloat16 b0h = __float2bfloat16_rn(b0f);
                __nv_bfloat16 b1h = __float2bfloat16_rn(b1f);
                ahi[ks][half * 2 + 0] = pack_bf16x2(__bfloat162float(a0h), __bfloat162float(a1h));
                ahi[ks][half * 2 + 1] = pack_bf16x2(__bfloat162float(b0h), __bfloat162float(b1h));
                alo[ks][half * 2 + 0] = pack_bf16x2(a0 - __bfloat162float(a0h),
                                                    a1 - __bfloat162float(a1h));
                alo[ks][half * 2 + 1] = pack_bf16x2(b0f - __bfloat162float(b0h),
                                                    b1f - __bfloat162float(b1h));
            }
        }
    }

    const int jj = tid >> 3;
    const int b  = tid & 7;
    float bh[4];
#pragma unroll
    for (int g = 0; g < 4; g++) bh[g] = __ldg(bhh + g * 256 + j0 + jj);

    // staging address (fragment-order, R12-validated mapping)
    const int kq   = jj & 15;
    const int cloc = jj >> 4;
    const int lt   = b * 4 + ((kq & 7) >> 1);
    const int wrd  = kq >> 3;
    const int byt  = kq & 1;
    char* stg_hi = smc + SM_STG + cloc * 512 + lt * 16 + wrd * 4 + byt * 2;

    // zero both B parities (h=0)
    for (int i = tid; i < (2 * PAR_SZ) / 4; i += 256) ((uint32_t*)smc)[i] = 0u;
    __syncthreads();
    asm volatile("barrier.cluster.arrive.aligned;" ::: "memory");
    asm volatile("barrier.cluster.wait.aligned;" ::: "memory");

    const int rl1 = (w << 4) + (lane >> 2);
    const int rl2 = rl1 + 8;
    const int n0  = (lane & 3) * 2;

    float c = 0.0f;
    float pf[4];
    {
        const int t0 = dir ? (TT - 1) : 0;
#pragma unroll
        for (int g = 0; g < 4; g++)
            pf[g] = __ldg(g_proj[dir] + ((size_t)t0 * G4 + g * 256 + j0 + jj) * BB + b0 + b);
    }

    for (int s = 0; s < TT; ++s) {
        const int t = dir ? (TT - 1 - s) : s;
        const int p = s & 1;

        // MMA on B[p]: one LDS.128 per chunk
        const char* bp = smc + p * PAR_SZ + lane * 16;
        float accA[4] = {0, 0, 0, 0}, accB[4] = {0, 0, 0, 0}, accC[4] = {0, 0, 0, 0};
#pragma unroll
        for (int ks = 0; ks < 16; ks++) {
            uint4 q = *(const uint4*)(bp + ks * 512);
            mma16816(accA, ahi[ks], q.x, q.y);
            mma16816(accB, ahi[ks], q.z, q.w);
            mma16816(accC, alo[ks], q.x, q.y);
        }
        gsm[rl1 * 9 + n0]     = accA[0] + accB[0] + accC[0];
        gsm[rl1 * 9 + n0 + 1] = accA[1] + accB[1] + accC[1];
        gsm[rl2 * 9 + n0]     = accA[2] + accB[2] + accC[2];
        gsm[rl2 * 9 + n0 + 1] = accA[3] + accB[3] + accC[3];
        __syncthreads();

        // cell: thread (jj, b)
        float gv[4];
#pragma unroll
        for (int g = 0; g < 4; g++)
            gv[g] = pf[g] + bh[g] + gsm[(g * 32 + jj) * 9 + b];
        float i_ = sigf(gv[0]);
        float f_ = sigf(gv[1]);
        float g_ = tanh_fast(gv[2]);
        float o_ = sigf(gv[3]);
        c = f_ * c + i_ * g_;
        float h = o_ * tanh_fast(c);

        g_hs[((size_t)t * 512 + dir * 256 + j0 + jj) * BB + b0 + b] = h;

        // stage own h in fragment order (hi word; lo word at +8B)
        {
            __nv_bfloat16 hh = __float2bfloat16_rn(h);
            __nv_bfloat16 hl = __float2bfloat16_rn(h - __bfloat162float(hh));
            *(__nv_bfloat16*)stg_hi       = hh;
            *(__nv_bfloat16*)(stg_hi + 8) = hl;
        }
        __syncthreads();

        // scatter own 1KB slice into B[p^1] of all 8 ranks (2 uint4/thread)
#pragma unroll
        for (int rep = 0; rep < 2; rep++) {
            int i = tid + rep * 256;
            int chunk = i & 63;
            int ro = i >> 6;
            uint4 v = *(const uint4*)(smc + SM_STG + chunk * 16);
            uint32_t dstoff = (uint32_t)((p ^ 1) * PAR_SZ + rank * 1024 + chunk * 16);
            st_cluster_f4(smem_u32 + dstoff, (uint32_t)((rank + ro) & 7), v);
        }

        // split cluster barrier; prefetch next proj between arrive and wait
        asm volatile("barrier.cluster.arrive.aligned;" ::: "memory");
        if (s + 1 < TT) {
            const int tn = dir ? (TT - 2 - s) : (s + 1);
#pragma unroll
            for (int g = 0; g < 4; g++)
                pf[g] = __ldg(g_proj[dir] + ((size_t)tn * G4 + g * 256 + j0 + jj) * BB + b0 + b);
        }
        asm volatile("barrier.cluster.wait.aligned;" ::: "memory");
    }
}

// ---------------- final FC ----------------
__global__ void __launch_bounds__(320) fc_kernel(
    const float* __restrict__ fcw, const float* __restrict__ fcb,
    float* __restrict__ out)
{
    const int t = blockIdx.x;
    const int o = threadIdx.x / 64;
    const int b = threadIdx.x & 63;
    const float* hp = g_hs + (size_t)t * 512 * BB + b;
    const float* wp = fcw + o * 512;
    float acc = 0.0f;
#pragma unroll 8
    for (int j = 0; j < 512; j++)
        acc += hp[(size_t)j * BB] * __ldg(wp + j);
    out[((size_t)b * TT + t) * 5 + o] = acc + __ldg(fcb + o);
}

// ---------------- launch ----------------
extern "C" void kernel_launch(void* const* d_in, const int* in_sizes, int n_in,
                              void* d_out, int out_size)
{
    const float* x      = (const float*)d_in[0];
    const float* wih_f  = (const float*)d_in[1];
    const float* whh_f  = (const float*)d_in[2];
    const float* bih_f  = (const float*)d_in[3];
    const float* bhh_f  = (const float*)d_in[4];
    const float* wih_b  = (const float*)d_in[5];
    const float* whh_b  = (const float*)d_in[6];
    const float* bih_b  = (const float*)d_in[7];
    const float* bhh_b  = (const float*)d_in[8];
    const float* fcw    = (const float*)d_in[9];
    const float* fcb    = (const float*)d_in[10];
    float* out = (float*)d_out;

    const int pm_smem = 2 * 19456;
    cudaFuncSetAttribute(proj_mma_kernel, cudaFuncAttributeMaxDynamicSharedMemorySize, pm_smem);
    cudaFuncSetAttribute(scan_kernel, cudaFuncAttributeMaxDynamicSharedMemorySize, SM_TOTAL);

    conv_x_kernel<<<TT, 256>>>(x);
    conv_w_kernel<<<dim3(G4, 2), 160>>>(wih_f, wih_b);

    dim3 pg(16, TT, 2);
    proj_mma_kernel<<<pg, 128, pm_smem>>>(bih_f, bih_b);

    scan_kernel<<<128, 256, SM_TOTAL>>>(whh_f, whh_b, bhh_f, bhh_b);

    fc_kernel<<<TT, 320>>>(fcw, fcb, out);
}

// round 15
// speedup vs baseline: 2.1742x; 1.2081x over previous
#include <cuda_runtime.h>
#include <cuda_bf16.h>
#include <cstdint>

// Problem constants
#define BB   64
#define TT   1024
#define HH   256
#define DIN  136
#define G4   1024
#define KP   144
#define CL   8
#define BPC  8
#define JPC  32

// ---------------- scratch ----------------
__device__ __align__(16) float g_proj[2][(size_t)TT * G4 * BB];
__device__ __align__(16) float g_hs[(size_t)TT * 2 * HH * BB];
__device__ __align__(16) __nv_bfloat16 g_xhi[(size_t)TT * BB * KP];
__device__ __align__(16) __nv_bfloat16 g_xlo[(size_t)TT * BB * KP];
__device__ __align__(16) __nv_bfloat16 g_whi[2][(size_t)G4 * KP];
__device__ __align__(16) __nv_bfloat16 g_wlo[2][(size_t)G4 * KP];

// ---------------- activations ----------------
__device__ __forceinline__ float sigf(float x) { return 1.0f / (1.0f + __expf(-x)); }
__device__ __forceinline__ float tanh_fast(float x) {
    float xx = fminf(fmaxf(x, -10.0f), 10.0f);
    float e = __expf(2.0f * xx);
    return (e - 1.0f) / (e + 1.0f);
}

// ---------------- DSMEM float4 store to peer rank ----------------
__device__ __forceinline__ void st_cluster_f4(uint32_t laddr, uint32_t rank, uint4 v) {
    asm volatile(
        "{\n\t.reg .b32 r;\n\t"
        "mapa.shared::cluster.u32 r, %0, %1;\n\t"
        "st.shared::cluster.v4.b32 [r], {%2, %3, %4, %5};\n\t}"
        :: "r"(laddr), "r"(rank), "r"(v.x), "r"(v.y), "r"(v.z), "r"(v.w) : "memory");
}

// ---------------- warp-level bf16 MMA ----------------
__device__ __forceinline__ void mma16816(float* d, const uint32_t* a,
                                         uint32_t b0, uint32_t b1) {
    asm volatile(
        "mma.sync.aligned.m16n8k16.row.col.f32.bf16.bf16.f32 "
        "{%0,%1,%2,%3}, {%4,%5,%6,%7}, {%8,%9}, {%0,%1,%2,%3};"
        : "+f"(d[0]), "+f"(d[1]), "+f"(d[2]), "+f"(d[3])
        : "r"(a[0]), "r"(a[1]), "r"(a[2]), "r"(a[3]), "r"(b0), "r"(b1));
}
__device__ __forceinline__ uint32_t pack_bf16x2(float lo, float hi) {
    __nv_bfloat162 t = __floats2bfloat162_rn(lo, hi);
    return *(uint32_t*)&t;
}

// ---------------- conversion kernels ----------------
__global__ void conv_x_kernel(const float* __restrict__ x) {
    const int t = blockIdx.x;
    for (int idx = threadIdx.x; idx < BB * KP; idx += 256) {
        int b = idx / KP, k = idx - b * KP;
        float v = (k < DIN) ? __ldg(x + ((size_t)b * TT + t) * DIN + k) : 0.0f;
        __nv_bfloat16 hi = __float2bfloat16_rn(v);
        __nv_bfloat16 lo = __float2bfloat16_rn(v - __bfloat162float(hi));
        size_t o = ((size_t)t * BB + b) * KP + k;
        g_xhi[o] = hi; g_xlo[o] = lo;
    }
}
__global__ void conv_w_kernel(const float* __restrict__ wf, const float* __restrict__ wb) {
    const int row = blockIdx.x;
    const int dir = blockIdx.y;
    const float* w = dir ? wb : wf;
    for (int k = threadIdx.x; k < KP; k += 160) {
        float v = (k < DIN) ? __ldg(w + (size_t)row * DIN + k) : 0.0f;
        __nv_bfloat16 hi = __float2bfloat16_rn(v);
        __nv_bfloat16 lo = __float2bfloat16_rn(v - __bfloat162float(hi));
        size_t o = (size_t)row * KP + k;
        g_whi[dir][o] = hi; g_wlo[dir][o] = lo;
    }
}

// ---------------- input projection via warp MMA (R10/R11, known-good) -------------
#define PBST 304
__global__ void __launch_bounds__(128, 3) proj_mma_kernel(
    const float* __restrict__ bih_f, const float* __restrict__ bih_b)
{
    extern __shared__ char psm[];
    char* sbhi = psm;
    char* sblo = psm + 19456;

    const int r0  = blockIdx.x * 64;
    const int t   = blockIdx.y;
    const int dir = blockIdx.z;
    const int tid = threadIdx.x;
    const int w   = tid >> 5;
    const int lane = tid & 31;

    const int m1 = (w << 4) + (lane >> 2);
    const int m2 = m1 + 8;
    const __nv_bfloat16* wh1 = g_whi[dir] + (size_t)(r0 + m1) * KP;
    const __nv_bfloat16* wh2 = g_whi[dir] + (size_t)(r0 + m2) * KP;
    const __nv_bfloat16* wl1 = g_wlo[dir] + (size_t)(r0 + m1) * KP;
    const __nv_bfloat16* wl2 = g_wlo[dir] + (size_t)(r0 + m2) * KP;
    uint32_t ahi[9][4], alo[9][4];
#pragma unroll
    for (int ch = 0; ch < 9; ch++) {
        int kb = ch * 16 + (lane & 3) * 2;
        ahi[ch][0] = *(const uint32_t*)(wh1 + kb);
        ahi[ch][1] = *(const uint32_t*)(wh2 + kb);
        ahi[ch][2] = *(const uint32_t*)(wh1 + kb + 8);
        ahi[ch][3] = *(const uint32_t*)(wh2 + kb + 8);
        alo[ch][0] = *(const uint32_t*)(wl1 + kb);
        alo[ch][1] = *(const uint32_t*)(wl2 + kb);
        alo[ch][2] = *(const uint32_t*)(wl1 + kb + 8);
        alo[ch][3] = *(const uint32_t*)(wl2 + kb + 8);
    }

    {
        const uint4* xh = (const uint4*)(g_xhi + (size_t)t * BB * KP);
        const uint4* xl = (const uint4*)(g_xlo + (size_t)t * BB * KP);
        for (int idx = tid; idx < 64 * 18; idx += 128) {
            int b = idx / 18, kk = idx - b * 18;
            uint4 vh = __ldg(xh + b * 18 + kk);
            uint4 vl = __ldg(xl + b * 18 + kk);
            *(uint4*)(sbhi + b * PBST + kk * 16) = vh;
            *(uint4*)(sblo + b * PBST + kk * 16) = vl;
        }
    }
    __syncthreads();

    float acc[8][4];
#pragma unroll
    for (int nt = 0; nt < 8; nt++)
#pragma unroll
        for (int i = 0; i < 4; i++) acc[nt][i] = 0.0f;

    const char* bhp = sbhi + (lane >> 2) * PBST + (lane & 3) * 4;
    const char* blp = sblo + (lane >> 2) * PBST + (lane & 3) * 4;
#pragma unroll
    for (int ch = 0; ch < 9; ch++) {
#pragma unroll
        for (int nt = 0; nt < 8; nt++) {
            int off = nt * 8 * PBST + ch * 32;
            uint32_t bh0 = *(const uint32_t*)(bhp + off);
            uint32_t bh1 = *(const uint32_t*)(bhp + off + 16);
            uint32_t bl0 = *(const uint32_t*)(blp + off);
            uint32_t bl1 = *(const uint32_t*)(blp + off + 16);
            mma16816(acc[nt], ahi[ch], bh0, bh1);
            mma16816(acc[nt], ahi[ch], bl0, bl1);
            mma16816(acc[nt], alo[ch], bh0, bh1);
        }
    }

    const float* bi = dir ? bih_b : bih_f;
    float bias1 = __ldg(bi + r0 + m1);
    float bias2 = __ldg(bi + r0 + m2);
    float* dst = g_proj[dir] + (size_t)t * G4 * BB;
    const int n0 = (lane & 3) * 2;
#pragma unroll
    for (int nt = 0; nt < 8; nt++) {
        int n = nt * 8 + n0;
        *(float2*)(dst + (size_t)(r0 + m1) * BB + n) =
            make_float2(acc[nt][0] + bias1, acc[nt][1] + bias1);
        *(float2*)(dst + (size_t)(r0 + m2) * BB + n) =
            make_float2(acc[nt][2] + bias2, acc[nt][3] + bias2);
    }
}

// ---------------- clustered scan: 2 interleaved recurrences per cluster -----------
// 8 clusters x 8 CTAs = 64 CTAs. Cluster = (dir, batch-group pair {g, g+4}) with
// SHARED W_hh A-fragments. Per super-step: recA then recB, ONE cluster barrier.
// SMEM: [0) B_A[2][8192]; [16384) B_B[2][8192]; [32768) stg 1KB (shared);
//       [33792) gsm [128][9] f32.
#define PAR_SZ   8192
#define SM_BB2   16384
#define SM_STG   32768
#define SM_GSM   33792
#define SM_TOTAL 38400

__global__ void __launch_bounds__(256, 1) __cluster_dims__(CL, 1, 1)
scan_kernel(const float* __restrict__ whh_f, const float* __restrict__ whh_b,
            const float* __restrict__ bhh_f, const float* __restrict__ bhh_b)
{
    extern __shared__ char smc[];
    float* gsm = (float*)(smc + SM_GSM);
    const uint32_t smem_u32 = (uint32_t)__cvta_generic_to_shared(smc);

    const int cid  = blockIdx.x >> 3;      // 0..7
    const int rank = blockIdx.x & 7;
    const int dir  = cid >> 2;             // 0..1
    const int b0A  = (cid & 3) * BPC;      // group A batches
    const int b0B  = b0A + 32;             // group B batches (same dir)
    const int j0   = rank * JPC;
    const float* whh = dir ? whh_b : whh_f;
    const float* bhh = dir ? bhh_b : bhh_f;
    const int tid  = threadIdx.x;
    const int w    = tid >> 5;
    const int lane = tid & 31;

    // W hi/lo A-fragments in registers (R9-validated layout; SHARED by A and B)
    uint32_t ahi[16][4], alo[16][4];
    {
        const int m1 = (w << 4) + (lane >> 2);
        const int m2 = m1 + 8;
        const int g1 = (m1 >> 5) * 256 + j0 + (m1 & 31);
        const int g2 = (m2 >> 5) * 256 + j0 + (m2 & 31);
        const float* wr1 = whh + (size_t)g1 * HH;
        const float* wr2 = whh + (size_t)g2 * HH;
#pragma unroll
        for (int ks = 0; ks < 16; ks++) {
            int kb = ks * 16 + (lane & 3) * 2;
#pragma unroll
            for (int half = 0; half < 2; half++) {
                int k = kb + half * 8;
                float a0 = __ldg(wr1 + k),  a1 = __ldg(wr1 + k + 1);
                float b0f = __ldg(wr2 + k), b1f = __ldg(wr2 + k + 1);
                __nv_bfloat16 a0h = __float2bfloat16_rn(a0);
                __nv_bfloat16 a1h = __float2bfloat16_rn(a1);
                __nv_bfloat16 b0h = __float2bfloat16_rn(b0f);
                __nv_bfloat16 b1h = __float2bfloat16_rn(b1f);
                ahi[ks][half * 2 + 0] = pack_bf16x2(__bfloat162float(a0h), __bfloat162float(a1h));
                ahi[ks][half * 2 + 1] = pack_bf16x2(__bfloat162float(b0h), __bfloat162float(b1h));
                alo[ks][half * 2 + 0] = pack_bf16x2(a0 - __bfloat162float(a0h),
                                                    a1 - __bfloat162float(a1h));
                alo[ks][half * 2 + 1] = pack_bf16x2(b0f - __bfloat162float(b0h),
                                                    b1f - __bfloat162float(b1h));
            }
        }
    }

    const int jj = tid >> 3;
    const int b  = tid & 7;
    float bh[4];
#pragma unroll
    for (int g = 0; g < 4; g++) bh[g] = __ldg(bhh + g * 256 + j0 + jj);

    // staging address (fragment-order, R12/R13-validated mapping)
    const int kq   = jj & 15;
    const int cloc = jj >> 4;
    const int lt   = b * 4 + ((kq & 7) >> 1);
    const int wrd  = kq >> 3;
    const int byt  = kq & 1;
    char* stg_hi = smc + SM_STG + cloc * 512 + lt * 16 + wrd * 4 + byt * 2;

    // zero all 4 B parities (h=0)
    for (int i = tid; i < (4 * PAR_SZ) / 4; i += 256) ((uint32_t*)smc)[i] = 0u;
    __syncthreads();
    asm volatile("barrier.cluster.arrive.aligned;" ::: "memory");
    asm volatile("barrier.cluster.wait.aligned;" ::: "memory");

    const int rl1 = (w << 4) + (lane >> 2);
    const int rl2 = rl1 + 8;
    const int n0  = (lane & 3) * 2;

    float cA = 0.0f, cB = 0.0f;
    float pfA[4], pfB[4];
    {
        const int t0 = dir ? (TT - 1) : 0;
#pragma unroll
        for (int g = 0; g < 4; g++) {
            pfA[g] = __ldg(g_proj[dir] + ((size_t)t0 * G4 + g * 256 + j0 + jj) * BB + b0A + b);
            pfB[g] = __ldg(g_proj[dir] + ((size_t)t0 * G4 + g * 256 + j0 + jj) * BB + b0B + b);
        }
    }

    for (int s = 0; s < TT; ++s) {
        const int t = dir ? (TT - 1 - s) : s;
        const int p = s & 1;

        // ================= recurrence A =================
        {
            const char* bp = smc + p * PAR_SZ + lane * 16;
            float accA[4] = {0, 0, 0, 0}, accB[4] = {0, 0, 0, 0}, accC[4] = {0, 0, 0, 0};
#pragma unroll
            for (int ks = 0; ks < 16; ks++) {
                uint4 q = *(const uint4*)(bp + ks * 512);
                mma16816(accA, ahi[ks], q.x, q.y);
                mma16816(accB, ahi[ks], q.z, q.w);
                mma16816(accC, alo[ks], q.x, q.y);
            }
            gsm[rl1 * 9 + n0]     = accA[0] + accB[0] + accC[0];
            gsm[rl1 * 9 + n0 + 1] = accA[1] + accB[1] + accC[1];
            gsm[rl2 * 9 + n0]     = accA[2] + accB[2] + accC[2];
            gsm[rl2 * 9 + n0 + 1] = accA[3] + accB[3] + accC[3];
            __syncthreads();

            float gv[4];
#pragma unroll
            for (int g = 0; g < 4; g++)
                gv[g] = pfA[g] + bh[g] + gsm[(g * 32 + jj) * 9 + b];
            float i_ = sigf(gv[0]);
            float f_ = sigf(gv[1]);
            float g_ = tanh_fast(gv[2]);
            float o_ = sigf(gv[3]);
            cA = f_ * cA + i_ * g_;
            float h = o_ * tanh_fast(cA);

            g_hs[((size_t)t * 512 + dir * 256 + j0 + jj) * BB + b0A + b] = h;

            __nv_bfloat16 hh = __float2bfloat16_rn(h);
            __nv_bfloat16 hl = __float2bfloat16_rn(h - __bfloat162float(hh));
            *(__nv_bfloat16*)stg_hi       = hh;
            *(__nv_bfloat16*)(stg_hi + 8) = hl;
            __syncthreads();

#pragma unroll
            for (int rep = 0; rep < 2; rep++) {
                int i = tid + rep * 256;
                int chunk = i & 63;
                int ro = i >> 6;
                uint4 v = *(const uint4*)(smc + SM_STG + chunk * 16);
                uint32_t dstoff = (uint32_t)((p ^ 1) * PAR_SZ + rank * 1024 + chunk * 16);
                st_cluster_f4(smem_u32 + dstoff, (uint32_t)((rank + ro) & 7), v);
            }
        }

        // ================= recurrence B =================
        {
            const char* bp = smc + SM_BB2 + p * PAR_SZ + lane * 16;
            float accA[4] = {0, 0, 0, 0}, accB[4] = {0, 0, 0, 0}, accC[4] = {0, 0, 0, 0};
#pragma unroll
            for (int ks = 0; ks < 16; ks++) {
                uint4 q = *(const uint4*)(bp + ks * 512);
                mma16816(accA, ahi[ks], q.x, q.y);
                mma16816(accB, ahi[ks], q.z, q.w);
                mma16816(accC, alo[ks], q.x, q.y);
            }
            __syncthreads();   // all threads done reading gsm(A) & stg(A)
            gsm[rl1 * 9 + n0]     = accA[0] + accB[0] + accC[0];
            gsm[rl1 * 9 + n0 + 1] = accA[1] + accB[1] + accC[1];
            gsm[rl2 * 9 + n0]     = accA[2] + accB[2] + accC[2];
            gsm[rl2 * 9 + n0 + 1] = accA[3] + accB[3] + accC[3];
            __syncthreads();

            float gv[4];
#pragma unroll
            for (int g = 0; g < 4; g++)
                gv[g] = pfB[g] + bh[g] + gsm[(g * 32 + jj) * 9 + b];
            float i_ = sigf(gv[0]);
            float f_ = sigf(gv[1]);
            float g_ = tanh_fast(gv[2]);
            float o_ = sigf(gv[3]);
            cB = f_ * cB + i_ * g_;
            float h = o_ * tanh_fast(cB);

            g_hs[((size_t)t * 512 + dir * 256 + j0 + jj) * BB + b0B + b] = h;

            __nv_bfloat16 hh = __float2bfloat16_rn(h);
            __nv_bfloat16 hl = __float2bfloat16_rn(h - __bfloat162float(hh));
            *(__nv_bfloat16*)stg_hi       = hh;
            *(__nv_bfloat16*)(stg_hi + 8) = hl;
            __syncthreads();

#pragma unroll
            for (int rep = 0; rep < 2; rep++) {
                int i = tid + rep * 256;
                int chunk = i & 63;
                int ro = i >> 6;
                uint4 v = *(const uint4*)(smc + SM_STG + chunk * 16);
                uint32_t dstoff = (uint32_t)(SM_BB2 + (p ^ 1) * PAR_SZ + rank * 1024 + chunk * 16);
                st_cluster_f4(smem_u32 + dstoff, (uint32_t)((rank + ro) & 7), v);
            }
        }

        // one cluster barrier per super-step; prefetch both proj sets in the gap
        asm volatile("barrier.cluster.arrive.aligned;" ::: "memory");
        if (s + 1 < TT) {
            const int tn = dir ? (TT - 2 - s) : (s + 1);
#pragma unroll
            for (int g = 0; g < 4; g++) {
                pfA[g] = __ldg(g_proj[dir] + ((size_t)tn * G4 + g * 256 + j0 + jj) * BB + b0A + b);
                pfB[g] = __ldg(g_proj[dir] + ((size_t)tn * G4 + g * 256 + j0 + jj) * BB + b0B + b);
            }
        }
        asm volatile("barrier.cluster.wait.aligned;" ::: "memory");
    }
}

// ---------------- final FC ----------------
__global__ void __launch_bounds__(320) fc_kernel(
    const float* __restrict__ fcw, const float* __restrict__ fcb,
    float* __restrict__ out)
{
    const int t = blockIdx.x;
    const int o = threadIdx.x / 64;
    const int b = threadIdx.x & 63;
    const float* hp = g_hs + (size_t)t * 512 * BB + b;
    const float* wp = fcw + o * 512;
    float acc = 0.0f;
#pragma unroll 8
    for (int j = 0; j < 512; j++)
        acc += hp[(size_t)j * BB] * __ldg(wp + j);
    out[((size_t)b * TT + t) * 5 + o] = acc + __ldg(fcb + o);
}

// ---------------- launch ----------------
extern "C" void kernel_launch(void* const* d_in, const int* in_sizes, int n_in,
                              void* d_out, int out_size)
{
    const float* x      = (const float*)d_in[0];
    const float* wih_f  = (const float*)d_in[1];
    const float* whh_f  = (const float*)d_in[2];
    const float* bih_f  = (const float*)d_in[3];
    const float* bhh_f  = (const float*)d_in[4];
    const float* wih_b  = (const float*)d_in[5];
    const float* whh_b  = (const float*)d_in[6];
    const float* bih_b  = (const float*)d_in[7];
    const float* bhh_b  = (const float*)d_in[8];
    const float* fcw    = (const float*)d_in[9];
    const float* fcb    = (const float*)d_in[10];
    float* out = (float*)d_out;

    const int pm_smem = 2 * 19456;
    cudaFuncSetAttribute(proj_mma_kernel, cudaFuncAttributeMaxDynamicSharedMemorySize, pm_smem);
    cudaFuncSetAttribute(scan_kernel, cudaFuncAttributeMaxDynamicSharedMemorySize, SM_TOTAL);

    conv_x_kernel<<<TT, 256>>>(x);
    conv_w_kernel<<<dim3(G4, 2), 160>>>(wih_f, wih_b);

    dim3 pg(16, TT, 2);
    proj_mma_kernel<<<pg, 128, pm_smem>>>(bih_f, bih_b);

    scan_kernel<<<64, 256, SM_TOTAL>>>(whh_f, whh_b, bhh_f, bhh_b);

    fc_kernel<<<TT, 320>>>(fcw, fcb, out);
}